// round 12
// baseline (speedup 1.0000x reference)
#include <cuda_runtime.h>
#include <cstdint>

// Problem constants
#define Cc 192
#define SHIFTc 4

// ---- gmem scratch (static __device__) ----
__device__ float g_qkv[(size_t)4096 * 3 * 64 * 192];  // [win][p][t][c]
__device__ float g_o[(size_t)4096 * 64 * 192];        // [win][t][c]

__device__ __forceinline__ float to_tf32(float f) {
    uint32_t u;
    asm("cvt.rna.tf32.f32 %0, %1;" : "=r"(u) : "f"(f));
    return __uint_as_float(u);
}

__device__ __forceinline__ void mma8(float* c, const uint32_t* a, const uint32_t* b) {
    asm volatile(
        "mma.sync.aligned.m16n8k8.row.col.f32.tf32.tf32.f32 "
        "{%0,%1,%2,%3}, {%4,%5,%6,%7}, {%8,%9}, {%0,%1,%2,%3};"
        : "+f"(c[0]), "+f"(c[1]), "+f"(c[2]), "+f"(c[3])
        : "r"(a[0]), "r"(a[1]), "r"(a[2]), "r"(a[3]),
          "r"(b[0]), "r"(b[1]));
}

// =====================================================================
// Kernel A: QKV GEMM, 2 windows/CTA (M=128), full-K A resident in smem,
// warp tile m64 x n48 (mt=4, nt=6) -> 4.67 smem-B/MMA.
// smem: A [128][196] = 100352 B ; Wt [32][200] = 25600 B
// =====================================================================
#define LDA 196
#define LDB 200
#define G_OFF_B 25088                    // floats (128*196)
#define G_SMEM_BYTES ((25088 + 6400) * 4)   // 125952

__global__ void __launch_bounds__(256, 1)
k_qkv(const float* __restrict__ x,
      const float* __restrict__ qkv_w,
      const float* __restrict__ qkv_b)
{
    extern __shared__ float smem[];
    float* Xs = smem;              // [128][196]
    float* Wt = smem + G_OFF_B;    // [32][200]

    const int tid  = threadIdx.x;
    const int warp = tid >> 5, lane = tid & 31;
    const int grp  = lane >> 2, tig = lane & 3;
    const int warp_m = warp >> 2;   // 0..1 (64 rows each)
    const int warp_n = warp & 3;    // 0..3 (48 cols each)
    const int bid = blockIdx.x;

    // ---- gather 2 windows with roll -> Xs[r][c] tf32 ----
    #pragma unroll 1
    for (int widx = 0; widx < 2; ++widx) {
        const int win = bid * 2 + widx;
        const int b = win >> 10, wy = (win >> 5) & 31, wx = win & 31;
        const int baseH = wy * 8 + SHIFTc, baseW = wx * 8 + SHIFTc;
        const float* xb = x + (size_t)b * Cc * 65536;
        #pragma unroll
        for (int i = 0; i < 48; ++i) {
            int idx = tid + i * 256;
            int c = idx >> 6, t = idx & 63;
            int ih = (baseH + (t >> 3)) & 255;
            int iw = (baseW + (t & 7)) & 255;
            Xs[(widx * 64 + t) * LDA + c] = to_tf32(xb[c * 65536 + ih * 256 + iw]);
        }
    }

    float acc[4][6][4];
    #pragma unroll
    for (int mt = 0; mt < 4; ++mt)
        #pragma unroll
        for (int nt = 0; nt < 6; ++nt)
            #pragma unroll
            for (int i = 0; i < 4; ++i) acc[mt][nt][i] = 0.0f;

    // prefetch B chunk 0 (pass 0, kc 0): 32x192 = 1536 float4, 6/thread
    float4 wreg[6];
    #pragma unroll
    for (int j = 0; j < 6; ++j) {
        int v4 = tid + j * 256;
        int row = v4 / 48, c4 = (v4 % 48) * 4;
        wreg[j] = *(const float4*)(qkv_w + (size_t)row * 576 + c4);
    }

    // flat loop: cc = pass*6 + kc  (pass 0..2, kc 0..5)
    #pragma unroll 1
    for (int cc = 0; cc < 18; ++cc) {
        const int kc = cc - (cc >= 6 ? (cc >= 12 ? 12 : 6) : 0);
        const int p  = (cc >= 12) ? 2 : (cc >= 6 ? 1 : 0);
        __syncthreads();   // all warps done reading Wt (prev chunk); A ready at cc=0
        #pragma unroll
        for (int j = 0; j < 6; ++j) {
            int v4 = tid + j * 256;
            int row = v4 / 48, c4 = (v4 % 48) * 4;
            float4 w = wreg[j];
            w.x = to_tf32(w.x); w.y = to_tf32(w.y);
            w.z = to_tf32(w.z); w.w = to_tf32(w.w);
            *(float4*)(Wt + row * LDB + c4) = w;
        }
        __syncthreads();
        if (cc < 17) {       // prefetch next chunk
            int cn = cc + 1;
            int kcn = cn - (cn >= 6 ? (cn >= 12 ? 12 : 6) : 0);
            int pn  = (cn >= 12) ? 2 : (cn >= 6 ? 1 : 0);
            #pragma unroll
            for (int j = 0; j < 6; ++j) {
                int v4 = tid + j * 256;
                int row = v4 / 48, c4 = (v4 % 48) * 4;
                wreg[j] = *(const float4*)(qkv_w + (size_t)(kcn * 32 + row) * 576 + pn * 192 + c4);
            }
        }

        #pragma unroll
        for (int ks = 0; ks < 4; ++ks) {
            const int kb = kc * 32 + ks * 8;
            uint32_t a[4][4];
            #pragma unroll
            for (int mt = 0; mt < 4; ++mt) {
                const float* ap = Xs + (warp_m * 64 + mt * 16 + grp) * LDA + kb + tig;
                a[mt][0] = __float_as_uint(ap[0]);
                a[mt][1] = __float_as_uint(ap[8 * LDA]);
                a[mt][2] = __float_as_uint(ap[4]);
                a[mt][3] = __float_as_uint(ap[8 * LDA + 4]);
            }
            uint32_t bb[6][2];
            #pragma unroll
            for (int nt = 0; nt < 6; ++nt) {
                const float* bp = Wt + (ks * 8 + tig) * LDB + warp_n * 48 + nt * 8 + grp;
                bb[nt][0] = __float_as_uint(bp[0]);
                bb[nt][1] = __float_as_uint(bp[4 * LDB]);
            }
            #pragma unroll
            for (int mt = 0; mt < 4; ++mt)
                #pragma unroll
                for (int nt = 0; nt < 6; ++nt)
                    mma8(acc[mt][nt], a[mt], bb[nt]);
        }

        if (kc == 5) {   // end of pass p: bias + store + reset acc
            #pragma unroll
            for (int nt = 0; nt < 6; ++nt) {
                int col = warp_n * 48 + nt * 8 + 2 * tig;
                float b0 = __ldg(qkv_b + p * 192 + col);
                float b1 = __ldg(qkv_b + p * 192 + col + 1);
                #pragma unroll
                for (int mt = 0; mt < 4; ++mt) {
                    int r = warp_m * 64 + mt * 16 + grp;
                    int win = bid * 2 + (r >> 6), t = r & 63;
                    float* dst = g_qkv + (size_t)win * 36864 + p * 12288 + t * 192 + col;
                    *(float2*)dst =
                        make_float2(to_tf32(acc[mt][nt][0] + b0), to_tf32(acc[mt][nt][1] + b1));
                    *(float2*)(dst + 8 * 192) =
                        make_float2(to_tf32(acc[mt][nt][2] + b0), to_tf32(acc[mt][nt][3] + b1));
                    acc[mt][nt][0] = 0.0f; acc[mt][nt][1] = 0.0f;
                    acc[mt][nt][2] = 0.0f; acc[mt][nt][3] = 0.0f;
                }
            }
        }
    }
}

// =====================================================================
// Kernel B: attention per (window, head) — unchanged from round 9.
// =====================================================================
#define LDH  36
#define LDVH 40
#define LDS2 68
#define B_SMEM_BYTES ((2304 + 2304 + 2560 + 4352) * 4)

__global__ void __launch_bounds__(128, 4)
k_attn()
{
    extern __shared__ float smemf[];
    float* Qh = smemf;
    float* Kh = smemf + 2304;
    float* Vh = smemf + 4608;
    float* S  = smemf + 7168;

    const int tid  = threadIdx.x;
    const int warp = tid >> 5, lane = tid & 31;
    const int grp  = lane >> 2, tig = lane & 3;
    const int win = blockIdx.x, h = blockIdx.y;

    {
        const float* src = g_qkv + (size_t)win * 36864 + h * 32;
        int r = tid >> 3, f4 = (tid & 7) * 4;
        #pragma unroll
        for (int it = 0; it < 4; ++it) {
            int t = r + it * 16;
            float4 q = *(const float4*)(src + t * 192 + f4);
            float4 k = *(const float4*)(src + 12288 + t * 192 + f4);
            float4 v = *(const float4*)(src + 24576 + t * 192 + f4);
            *(float4*)(Qh + t * LDH + f4)  = q;
            *(float4*)(Kh + t * LDH + f4)  = k;
            *(float4*)(Vh + t * LDVH + f4) = v;
        }
    }
    __syncthreads();

    float sacc[8][4];
    #pragma unroll
    for (int nt = 0; nt < 8; ++nt)
        #pragma unroll
        for (int i = 0; i < 4; ++i) sacc[nt][i] = 0.0f;

    #pragma unroll
    for (int ks = 0; ks < 4; ++ks) {
        int kb = ks * 8;
        uint32_t a[4];
        const float* ap = Qh + (warp * 16 + grp) * LDH + kb + tig;
        a[0] = __float_as_uint(ap[0]);
        a[1] = __float_as_uint(ap[8 * LDH]);
        a[2] = __float_as_uint(ap[4]);
        a[3] = __float_as_uint(ap[8 * LDH + 4]);
        #pragma unroll
        for (int nt = 0; nt < 8; ++nt) {
            uint32_t bb[2];
            const float* bp = Kh + (nt * 8 + grp) * LDH + kb + tig;
            bb[0] = __float_as_uint(bp[0]);
            bb[1] = __float_as_uint(bp[4]);
            mma8(sacc[nt], a, bb);
        }
    }
    const float scale = 0.17677669529663687f;
    #pragma unroll
    for (int nt = 0; nt < 8; ++nt) {
        int col = nt * 8 + 2 * tig;
        int r0 = warp * 16 + grp;
        *(float2*)(S + r0 * LDS2 + col) =
            make_float2(sacc[nt][0] * scale, sacc[nt][1] * scale);
        *(float2*)(S + (r0 + 8) * LDS2 + col) =
            make_float2(sacc[nt][2] * scale, sacc[nt][3] * scale);
    }
    __syncwarp();

    #pragma unroll 1
    for (int rr = 0; rr < 16; ++rr) {
        int row = warp * 16 + rr;
        float v0 = S[row * LDS2 + lane];
        float v1 = S[row * LDS2 + 32 + lane];
        float m = fmaxf(v0, v1);
        #pragma unroll
        for (int off = 16; off > 0; off >>= 1)
            m = fmaxf(m, __shfl_xor_sync(0xFFFFFFFFu, m, off));
        float e0 = __expf(v0 - m);
        float e1 = __expf(v1 - m);
        float s = e0 + e1;
        #pragma unroll
        for (int off = 16; off > 0; off >>= 1)
            s += __shfl_xor_sync(0xFFFFFFFFu, s, off);
        float inv = __frcp_rn(s);
        S[row * LDS2 + lane]      = to_tf32(e0 * inv);
        S[row * LDS2 + 32 + lane] = to_tf32(e1 * inv);
    }
    __syncwarp();

    float oacc[4][4];
    #pragma unroll
    for (int nt = 0; nt < 4; ++nt)
        #pragma unroll
        for (int i = 0; i < 4; ++i) oacc[nt][i] = 0.0f;

    #pragma unroll
    for (int ks = 0; ks < 8; ++ks) {
        uint32_t a[4];
        const float* ap = S + (warp * 16 + grp) * LDS2 + ks * 8 + tig;
        a[0] = __float_as_uint(ap[0]);
        a[1] = __float_as_uint(ap[8 * LDS2]);
        a[2] = __float_as_uint(ap[4]);
        a[3] = __float_as_uint(ap[8 * LDS2 + 4]);
        #pragma unroll
        for (int nt = 0; nt < 4; ++nt) {
            uint32_t bb[2];
            const float* bp = Vh + (ks * 8 + tig) * LDVH + nt * 8 + grp;
            bb[0] = __float_as_uint(bp[0]);
            bb[1] = __float_as_uint(bp[4 * LDVH]);
            mma8(oacc[nt], a, bb);
        }
    }
    float* dst = g_o + (size_t)win * 12288 + h * 32;
    #pragma unroll
    for (int nt = 0; nt < 4; ++nt) {
        int col = nt * 8 + 2 * tig;
        int r0 = warp * 16 + grp;
        *(float2*)(dst + r0 * 192 + col) =
            make_float2(to_tf32(oacc[nt][0]), to_tf32(oacc[nt][1]));
        *(float2*)(dst + (r0 + 8) * 192 + col) =
            make_float2(to_tf32(oacc[nt][2]), to_tf32(oacc[nt][3]));
    }
}

// =====================================================================
// Kernel C: proj GEMM, 2 windows/CTA, full-K A resident, warp tile m64 x n48,
// roll-scatter epilogue straight from registers.
// =====================================================================
__global__ void __launch_bounds__(256, 1)
k_proj(const float* __restrict__ proj_w,
       const float* __restrict__ proj_b,
       float* __restrict__ out)
{
    extern __shared__ float smem[];
    float* Os = smem;              // [128][196]
    float* Wt = smem + G_OFF_B;    // [32][200]

    const int tid  = threadIdx.x;
    const int warp = tid >> 5, lane = tid & 31;
    const int grp  = lane >> 2, tig = lane & 3;
    const int warp_m = warp >> 2;
    const int warp_n = warp & 3;
    const int bid = blockIdx.x;

    // stage A: O tiles of 2 windows (already tf32), float4 coalesced
    #pragma unroll 1
    for (int widx = 0; widx < 2; ++widx) {
        const float* src = g_o + (size_t)(bid * 2 + widx) * 12288;
        #pragma unroll
        for (int i = 0; i < 12; ++i) {
            int idx = tid + i * 256;          // 3072 float4 per window
            int t = idx / 48, q4 = (idx % 48) * 4;
            *(float4*)(Os + (widx * 64 + t) * LDA + q4) = *(const float4*)(src + t * 192 + q4);
        }
    }

    float acc[4][6][4];
    #pragma unroll
    for (int mt = 0; mt < 4; ++mt)
        #pragma unroll
        for (int nt = 0; nt < 6; ++nt)
            #pragma unroll
            for (int i = 0; i < 4; ++i) acc[mt][nt][i] = 0.0f;

    float4 wreg[6];
    #pragma unroll
    for (int j = 0; j < 6; ++j)
        wreg[j] = ((const float4*)proj_w)[tid + j * 256];

    #pragma unroll 1
    for (int kc = 0; kc < 6; ++kc) {
        __syncthreads();
        #pragma unroll
        for (int j = 0; j < 6; ++j) {
            int v4 = tid + j * 256;
            int row = v4 / 48, c4 = (v4 % 48) * 4;
            float4 w = wreg[j];
            w.x = to_tf32(w.x); w.y = to_tf32(w.y);
            w.z = to_tf32(w.z); w.w = to_tf32(w.w);
            *(float4*)(Wt + row * LDB + c4) = w;
        }
        __syncthreads();
        if (kc < 5) {
            #pragma unroll
            for (int j = 0; j < 6; ++j)
                wreg[j] = ((const float4*)(proj_w + (kc + 1) * 6144))[tid + j * 256];
        }

        #pragma unroll
        for (int ks = 0; ks < 4; ++ks) {
            const int kb = kc * 32 + ks * 8;
            uint32_t a[4][4];
            #pragma unroll
            for (int mt = 0; mt < 4; ++mt) {
                const float* ap = Os + (warp_m * 64 + mt * 16 + grp) * LDA + kb + tig;
                a[mt][0] = __float_as_uint(ap[0]);
                a[mt][1] = __float_as_uint(ap[8 * LDA]);
                a[mt][2] = __float_as_uint(ap[4]);
                a[mt][3] = __float_as_uint(ap[8 * LDA + 4]);
            }
            uint32_t bb[6][2];
            #pragma unroll
            for (int nt = 0; nt < 6; ++nt) {
                const float* bp = Wt + (ks * 8 + tig) * LDB + warp_n * 48 + nt * 8 + grp;
                bb[nt][0] = __float_as_uint(bp[0]);
                bb[nt][1] = __float_as_uint(bp[4 * LDB]);
            }
            #pragma unroll
            for (int mt = 0; mt < 4; ++mt)
                #pragma unroll
                for (int nt = 0; nt < 6; ++nt)
                    mma8(acc[mt][nt], a[mt], bb[nt]);
        }
    }

    // epilogue: bias + roll-scatter straight from registers (NCHW)
    #pragma unroll
    for (int nt = 0; nt < 6; ++nt) {
        int col = warp_n * 48 + nt * 8 + 2 * tig;
        float b0 = __ldg(proj_b + col);
        float b1 = __ldg(proj_b + col + 1);
        #pragma unroll
        for (int mt = 0; mt < 4; ++mt) {
            int r = warp_m * 64 + mt * 16 + grp;
            int win = bid * 2 + (r >> 6);
            int b = win >> 10, wy = (win >> 5) & 31, wx = win & 31;
            int t0 = r & 63;
            int oh0 = ((wy * 8 + SHIFTc) + (t0 >> 3)) & 255;
            int oh1 = ((wy * 8 + SHIFTc) + ((t0 + 8) >> 3)) & 255;
            int ow  = ((wx * 8 + SHIFTc) + (t0 & 7)) & 255;
            float* o0 = out + (size_t)b * Cc * 65536 + (size_t)col * 65536;
            float* o1 = o0 + 65536;
            o0[oh0 * 256 + ow] = acc[mt][nt][0] + b0;
            o1[oh0 * 256 + ow] = acc[mt][nt][1] + b1;
            o0[oh1 * 256 + ow] = acc[mt][nt][2] + b0;
            o1[oh1 * 256 + ow] = acc[mt][nt][3] + b1;
        }
    }
}

extern "C" void kernel_launch(void* const* d_in, const int* in_sizes, int n_in,
                              void* d_out, int out_size)
{
    const float* x      = (const float*)d_in[0];
    const float* qkv_w  = (const float*)d_in[1];
    const float* qkv_b  = (const float*)d_in[2];
    const float* proj_w = (const float*)d_in[3];
    const float* proj_b = (const float*)d_in[4];
    float* out = (float*)d_out;

    cudaFuncSetAttribute(k_qkv,  cudaFuncAttributeMaxDynamicSharedMemorySize, G_SMEM_BYTES);
    cudaFuncSetAttribute(k_attn, cudaFuncAttributeMaxDynamicSharedMemorySize, B_SMEM_BYTES);
    cudaFuncSetAttribute(k_proj, cudaFuncAttributeMaxDynamicSharedMemorySize, G_SMEM_BYTES);

    k_qkv<<<2048, 256, G_SMEM_BYTES>>>(x, qkv_w, qkv_b);
    dim3 gb(4096, 6);
    k_attn<<<gb, 128, B_SMEM_BYTES>>>();
    k_proj<<<2048, 256, G_SMEM_BYTES>>>(proj_w, proj_b, out);
}